// round 6
// baseline (speedup 1.0000x reference)
#include <cuda_runtime.h>

#define NN   50000
#define EE   320000
#define RR   3
#define IN_F 768
#define HID  256
#define OUT_F 64

// ---------------- static scratch (no allocation allowed) ----------------
__device__ float    g_h   [(size_t)NN * HID];
__device__ float    g_h2  [(size_t)NN * HID];
__device__ float    g_xw  [(size_t)RR * NN * HID];
__device__ float    g_aq  [(size_t)RR * NN];
__device__ float    g_ak  [(size_t)RR * NN];
__device__ float    g_alpha[EE];
__device__ unsigned g_menc[NN];
__device__ float    g_denom[NN];
__device__ float    g_h3  [(size_t)NN * OUT_F];

// ---------------- ordered-uint encoding for float atomicMax ----------------
__device__ __forceinline__ unsigned fenc(float f) {
    unsigned u = __float_as_uint(f);
    return (u & 0x80000000u) ? ~u : (u | 0x80000000u);
}
__device__ __forceinline__ float fdec(unsigned u) {
    return (u & 0x80000000u) ? __uint_as_float(u & 0x7fffffffu) : __uint_as_float(~u);
}
#define ENC_NEG_INF 0x007fffffu   // fenc(-inf)

// ---------------- double-buffered tiled SGEMM (+ optional fused q/k dots) ----
// C = [relu](A@B + bias), batched over blockIdx.z.
// A: [M,K] row-major (shared across batch), B: [K,N] (+z*strideB), C: [M,N] (+z*strideC)
// If qv != nullptr: additionally accumulate aq[z*NN + row] += C_row · qv and
// ak[z*NN + row] += C_row · kv via atomics (requires aq/ak pre-zeroed).
#define BM 128
#define BN 128
#define BK 16
#define TM 8
#define TN 8
#define AP (BM + 4)   // padded A-tile row stride: 132 floats -> 4-way STS conflict becomes 2-way
__global__ __launch_bounds__(256) void sgemm_kernel(
    const float* __restrict__ A, const float* __restrict__ B, float* __restrict__ C,
    const float* __restrict__ bias, int M, int N, int K, int do_relu,
    long long strideB, long long strideC,
    const float* __restrict__ qv, const float* __restrict__ kv,
    float* __restrict__ aq, float* __restrict__ ak)
{
    __shared__ float As[2][BK][AP];
    __shared__ float Bs[2][BK][BN];

    const float* Bz = B + (long long)blockIdx.z * strideB;
    float*       Cz = C + (long long)blockIdx.z * strideC;

    const int tid  = threadIdx.x;
    const int row0 = blockIdx.y * BM;
    const int col0 = blockIdx.x * BN;
    const int ty   = tid >> 4;   // 0..15
    const int tx   = tid & 15;   // 0..15

    // per-thread load coordinates (2 chunks each for A and B)
    const int a_r[2]  = { (tid + 0)   >> 2, (tid + 256) >> 2 };
    const int a_c4[2] = { ((tid + 0) & 3) * 4, ((tid + 256) & 3) * 4 };
    const int b_r[2]  = { (tid + 0)   >> 5, (tid + 256) >> 5 };
    const int b_c4[2] = { ((tid + 0) & 31) * 4, ((tid + 256) & 31) * 4 };

    float acc[TM][TN];
#pragma unroll
    for (int i = 0; i < TM; i++)
#pragma unroll
        for (int j = 0; j < TN; j++) acc[i][j] = 0.f;

    const int KT = K / BK;               // K is always a multiple of 16 here

    float4 ra[2], rb[2];

    // ---- preload tile 0 into buffer 0 ----
#pragma unroll
    for (int it = 0; it < 2; it++) {
        int gr = row0 + a_r[it];
        ra[it] = make_float4(0.f, 0.f, 0.f, 0.f);
        if (gr < M) ra[it] = *(const float4*)(A + (long long)gr * K + a_c4[it]);
        rb[it] = make_float4(0.f, 0.f, 0.f, 0.f);
        int gc = col0 + b_c4[it];
        if (gc < N) rb[it] = *(const float4*)(Bz + (long long)b_r[it] * N + gc);
    }
#pragma unroll
    for (int it = 0; it < 2; it++) {
        As[0][a_c4[it] + 0][a_r[it]] = ra[it].x;
        As[0][a_c4[it] + 1][a_r[it]] = ra[it].y;
        As[0][a_c4[it] + 2][a_r[it]] = ra[it].z;
        As[0][a_c4[it] + 3][a_r[it]] = ra[it].w;
        *(float4*)&Bs[0][b_r[it]][b_c4[it]] = rb[it];
    }
    __syncthreads();

    for (int kt = 0; kt < KT; kt++) {
        const int p = kt & 1;
        const int k_next = (kt + 1) * BK;

        // issue next-tile global loads (overlap with compute below)
        if (kt + 1 < KT) {
#pragma unroll
            for (int it = 0; it < 2; it++) {
                int gr = row0 + a_r[it];
                ra[it] = make_float4(0.f, 0.f, 0.f, 0.f);
                if (gr < M) ra[it] = *(const float4*)(A + (long long)gr * K + k_next + a_c4[it]);
                rb[it] = make_float4(0.f, 0.f, 0.f, 0.f);
                int gc = col0 + b_c4[it];
                if (gc < N) rb[it] = *(const float4*)(Bz + (long long)(k_next + b_r[it]) * N + gc);
            }
        }

        // compute from buffer p
#pragma unroll
        for (int kk = 0; kk < BK; kk++) {
            float a[TM], b[TN];
            float4 a0 = *(const float4*)&As[p][kk][ty * TM];
            float4 a1 = *(const float4*)&As[p][kk][ty * TM + 4];
            a[0]=a0.x; a[1]=a0.y; a[2]=a0.z; a[3]=a0.w;
            a[4]=a1.x; a[5]=a1.y; a[6]=a1.z; a[7]=a1.w;
            float4 b0 = *(const float4*)&Bs[p][kk][tx * TN];
            float4 b1 = *(const float4*)&Bs[p][kk][tx * TN + 4];
            b[0]=b0.x; b[1]=b0.y; b[2]=b0.z; b[3]=b0.w;
            b[4]=b1.x; b[5]=b1.y; b[6]=b1.z; b[7]=b1.w;
#pragma unroll
            for (int i = 0; i < TM; i++)
#pragma unroll
                for (int j = 0; j < TN; j++)
                    acc[i][j] += a[i] * b[j];
        }

        // write next tile into the other buffer, one sync
        if (kt + 1 < KT) {
            const int q = 1 - p;
#pragma unroll
            for (int it = 0; it < 2; it++) {
                As[q][a_c4[it] + 0][a_r[it]] = ra[it].x;
                As[q][a_c4[it] + 1][a_r[it]] = ra[it].y;
                As[q][a_c4[it] + 2][a_r[it]] = ra[it].z;
                As[q][a_c4[it] + 3][a_r[it]] = ra[it].w;
                *(float4*)&Bs[q][b_r[it]][b_c4[it]] = rb[it];
            }
            __syncthreads();
        }
    }

    // ---- main store ----
#pragma unroll
    for (int i = 0; i < TM; i++) {
        int gr = row0 + ty * TM + i;
        if (gr >= M) continue;
#pragma unroll
        for (int j = 0; j < TN; j += 4) {
            int gc = col0 + tx * TN + j;
            if (gc >= N) continue;
            float4 v;
            v.x = acc[i][j + 0];
            v.y = acc[i][j + 1];
            v.z = acc[i][j + 2];
            v.w = acc[i][j + 3];
            if (bias) {
                v.x += __ldg(bias + gc + 0); v.y += __ldg(bias + gc + 1);
                v.z += __ldg(bias + gc + 2); v.w += __ldg(bias + gc + 3);
            }
            if (do_relu) {
                v.x = fmaxf(v.x, 0.f); v.y = fmaxf(v.y, 0.f);
                v.z = fmaxf(v.z, 0.f); v.w = fmaxf(v.w, 0.f);
            }
            *(float4*)(Cz + (long long)gr * N + gc) = v;
        }
    }

    // ---- fused q/k projection epilogue (conv GEMMs only) ----
    // Rows live in registers; dot with q/k slices, reduce across the 16 tx
    // lanes covering the full BN tile, atomically accumulate partial sums.
    if (qv) {
        float* aqz = aq + (long long)blockIdx.z * NN;
        float* akz = ak + (long long)blockIdx.z * NN;
        float qreg[TN], kreg[TN];
#pragma unroll
        for (int j = 0; j < TN; j++) {
            qreg[j] = __ldg(qv + col0 + tx * TN + j);
            kreg[j] = __ldg(kv + col0 + tx * TN + j);
        }
#pragma unroll
        for (int i = 0; i < TM; i++) {
            float sq = 0.f, sk = 0.f;
#pragma unroll
            for (int j = 0; j < TN; j++) {
                sq += acc[i][j] * qreg[j];
                sk += acc[i][j] * kreg[j];
            }
            // reduce over the 16-lane tx group (lanes 0-15 / 16-31 of each warp)
#pragma unroll
            for (int off = 8; off; off >>= 1) {
                sq += __shfl_xor_sync(0xffffffffu, sq, off);
                sk += __shfl_xor_sync(0xffffffffu, sk, off);
            }
            if (tx == 0) {
                int gr = row0 + ty * TM + i;
                if (gr < M) {
                    atomicAdd(aqz + gr, sq);
                    atomicAdd(akz + gr, sk);
                }
            }
        }
    }
}

// ---------------- per-conv init: aq/ak zero, segment-max/denom, bias prefill ----
__global__ void conv_init_kernel(float* __restrict__ aq, float* __restrict__ ak,
                                 unsigned* __restrict__ menc, float* __restrict__ denom,
                                 float4* __restrict__ acc4, const float4* __restrict__ bias4)
{
    long long i = (long long)blockIdx.x * blockDim.x + threadIdx.x;
    if (i < RR * NN) { aq[i] = 0.f; ak[i] = 0.f; }
    if (i < NN) { menc[i] = ENC_NEG_INF; denom[i] = 0.f; }
    if (i < (long long)NN * (HID / 4)) acc4[i] = __ldg(bias4 + (i & (HID / 4 - 1)));
}

// ---------------- edge pass 1: alpha + segment max ----------------
__global__ void alpha_kernel(const int* __restrict__ src, const int* __restrict__ dst,
                             const int* __restrict__ et, const float* __restrict__ aq,
                             const float* __restrict__ ak, float* __restrict__ alpha,
                             unsigned* __restrict__ menc)
{
    int e = blockIdx.x * blockDim.x + threadIdx.x;
    if (e >= EE) return;
    int r = __ldg(et + e), d = __ldg(dst + e), s = __ldg(src + e);
    float a = __ldg(aq + (long long)r * NN + d) + __ldg(ak + (long long)r * NN + s);
    a = (a > 0.f) ? a : 0.2f * a;       // leaky_relu slope 0.2
    alpha[e] = a;
    atomicMax(menc + d, fenc(a));
}

// ---------------- edge pass 2: exp + segment sum ----------------
__global__ void ea_kernel(const int* __restrict__ dst, float* __restrict__ alpha,
                          const unsigned* __restrict__ menc, float* __restrict__ denom)
{
    int e = blockIdx.x * blockDim.x + threadIdx.x;
    if (e >= EE) return;
    int d = __ldg(dst + e);
    float v = __expf(alpha[e] - fdec(__ldg(menc + d)));
    alpha[e] = v;                        // overwrite with exp value
    atomicAdd(denom + d, v);
}

// ---------------- edge pass 3: weighted scatter (warp per edge, 128b red) ----------------
// Target buffer is pre-initialized with the layer bias, so no epilogue pass needed.
__global__ void scatter_kernel(const int* __restrict__ src, const int* __restrict__ dst,
                               const int* __restrict__ et, const float* __restrict__ ea,
                               const float* __restrict__ denom, const float* __restrict__ xw,
                               float* __restrict__ acc)
{
    int gtid = blockIdx.x * blockDim.x + threadIdx.x;
    int e    = gtid >> 5;
    int lane = gtid & 31;
    if (e >= EE) return;
    int d = __ldg(dst + e), s = __ldg(src + e), r = __ldg(et + e);
    float coef = __ldg(ea + e) / (__ldg(denom + d) + 1e-16f);
    const float4* row = (const float4*)(xw + ((long long)r * NN + s) * HID);
    float4*       out = (float4*)(acc + (long long)d * HID);
    // issue both loads first (MLP=2), then fire-and-forget reductions
    float4 v0 = __ldg(row + lane);
    float4 v1 = __ldg(row + lane + 32);
    v0.x *= coef; v0.y *= coef; v0.z *= coef; v0.w *= coef;
    v1.x *= coef; v1.y *= coef; v1.z *= coef; v1.w *= coef;
    asm volatile("red.global.add.v4.f32 [%0], {%1, %2, %3, %4};"
                 :: "l"(out + lane), "f"(v0.x), "f"(v0.y), "f"(v0.z), "f"(v0.w)
                 : "memory");
    asm volatile("red.global.add.v4.f32 [%0], {%1, %2, %3, %4};"
                 :: "l"(out + lane + 32), "f"(v1.x), "f"(v1.y), "f"(v1.z), "f"(v1.w)
                 : "memory");
}

// ---------------- final classifier: warp per node ----------------
__global__ void cls_kernel(const float* __restrict__ h3, const float* __restrict__ w_cls,
                           const float* __restrict__ b_cls, float* __restrict__ out)
{
    int gtid = blockIdx.x * blockDim.x + threadIdx.x;
    int n    = gtid >> 5;
    int lane = gtid & 31;
    if (n >= NN) return;
    const float* row = h3 + (long long)n * OUT_F;
    float s0 = 0.f, s1 = 0.f;
#pragma unroll
    for (int i = 0; i < OUT_F / 32; i++) {
        int o = lane + i * 32;
        float v = __ldg(row + o);
        s0 += v * __ldg(w_cls + 2 * o + 0);
        s1 += v * __ldg(w_cls + 2 * o + 1);
    }
#pragma unroll
    for (int off = 16; off; off >>= 1) {
        s0 += __shfl_xor_sync(0xffffffffu, s0, off);
        s1 += __shfl_xor_sync(0xffffffffu, s1, off);
    }
    if (lane == 0) {
        out[(long long)n * 2 + 0] = s0 + b_cls[0];
        out[(long long)n * 2 + 1] = s1 + b_cls[1];
    }
}

// ---------------- host orchestration ----------------
extern "C" void kernel_launch(void* const* d_in, const int* in_sizes, int n_in,
                              void* d_out, int out_size)
{
    const float* x     = (const float*)d_in[0];
    const int*   ei    = (const int*)  d_in[1];
    const int*   et    = (const int*)  d_in[2];
    const float* w_in  = (const float*)d_in[3];
    const float* b_in  = (const float*)d_in[4];
    const float* c1w   = (const float*)d_in[5];
    const float* c1q   = (const float*)d_in[6];
    const float* c1k   = (const float*)d_in[7];
    const float* c1b   = (const float*)d_in[8];
    const float* c2w   = (const float*)d_in[9];
    const float* c2q   = (const float*)d_in[10];
    const float* c2k   = (const float*)d_in[11];
    const float* c2b   = (const float*)d_in[12];
    const float* w_out = (const float*)d_in[13];
    const float* b_out = (const float*)d_in[14];
    const float* w_cls = (const float*)d_in[15];
    const float* b_cls = (const float*)d_in[16];
    float* out = (float*)d_out;

    const int* src = ei;
    const int* dst = ei + EE;

    float *p_h, *p_h2, *p_xw, *p_aq, *p_ak, *p_alpha, *p_denom, *p_h3;
    unsigned* p_menc;
    cudaGetSymbolAddress((void**)&p_h,    g_h);
    cudaGetSymbolAddress((void**)&p_h2,   g_h2);
    cudaGetSymbolAddress((void**)&p_xw,   g_xw);
    cudaGetSymbolAddress((void**)&p_aq,   g_aq);
    cudaGetSymbolAddress((void**)&p_ak,   g_ak);
    cudaGetSymbolAddress((void**)&p_alpha,g_alpha);
    cudaGetSymbolAddress((void**)&p_menc, g_menc);
    cudaGetSymbolAddress((void**)&p_denom,g_denom);
    cudaGetSymbolAddress((void**)&p_h3,   g_h3);

    const int GY = (NN + BM - 1) / BM;         // 391
    const long long nvec = (long long)NN * (HID / 4);

    // h = relu(x @ w_in + b_in)
    sgemm_kernel<<<dim3((HID + BN - 1) / BN, GY, 1), 256>>>(
        x, w_in, p_h, b_in, NN, HID, IN_F, 1, 0, 0,
        nullptr, nullptr, nullptr, nullptr);

    // two RGAT convs
    const float* cw[2] = {c1w, c2w};
    const float* cq[2] = {c1q, c2q};
    const float* ck[2] = {c1k, c2k};
    const float* cb[2] = {c1b, c2b};
    float* hin[2]  = {p_h,  p_h2};
    float* hout[2] = {p_h2, p_h};

    for (int l = 0; l < 2; l++) {
        // init aq/ak (epilogue accumulates atomically), segment max / denom,
        // and pre-fill output with broadcast bias — all BEFORE the GEMM.
        conv_init_kernel<<<(int)((nvec + 255) / 256), 256>>>(
            p_aq, p_ak, p_menc, p_denom, (float4*)hout[l], (const float4*)cb[l]);
        // xw[r] = h @ W[r]  (batched over z) with fused aq/ak epilogue
        sgemm_kernel<<<dim3((HID + BN - 1) / BN, GY, RR), 256>>>(
            hin[l], cw[l], p_xw, nullptr, NN, HID, HID, 0,
            (long long)HID * HID, (long long)NN * HID,
            cq[l], ck[l], p_aq, p_ak);
        alpha_kernel<<<(EE + 255) / 256, 256>>>(src, dst, et, p_aq, p_ak, p_alpha, p_menc);
        ea_kernel<<<(EE + 255) / 256, 256>>>(dst, p_alpha, p_menc, p_denom);
        scatter_kernel<<<((size_t)EE * 32 + 255) / 256, 256>>>(
            src, dst, et, p_alpha, p_denom, p_xw, hout[l]);
    }

    // h3 = relu(h @ w_out + b_out)  (input is hout[1] == p_h)
    sgemm_kernel<<<dim3(1, GY, 1), 256>>>(
        p_h, w_out, p_h3, b_out, NN, OUT_F, HID, 1, 0, 0,
        nullptr, nullptr, nullptr, nullptr);
    // out = h3 @ w_cls + b_cls
    cls_kernel<<<((size_t)NN * 32 + 255) / 256, 256>>>(p_h3, w_cls, b_cls, out);
}

// round 9
// speedup vs baseline: 1.2430x; 1.2430x over previous
#include <cuda_runtime.h>
#include <cstdint>

#define NN   50000
#define EE   320000
#define RR   3
#define IN_F 768
#define HID  256
#define OUT_F 64

// ---------------- static scratch (no allocation allowed) ----------------
__device__ float    g_h   [(size_t)NN * HID];
__device__ float    g_h2  [(size_t)NN * HID];
__device__ float    g_xw  [(size_t)RR * NN * HID];
__device__ float    g_aq  [(size_t)RR * NN];
__device__ float    g_ak  [(size_t)RR * NN];
__device__ float    g_alpha[EE];
__device__ unsigned g_menc[NN];
__device__ float    g_denom[NN];
__device__ float    g_h3  [(size_t)NN * OUT_F];

// ---------------- ordered-uint encoding for float atomicMax ----------------
__device__ __forceinline__ unsigned fenc(float f) {
    unsigned u = __float_as_uint(f);
    return (u & 0x80000000u) ? ~u : (u | 0x80000000u);
}
__device__ __forceinline__ float fdec(unsigned u) {
    return (u & 0x80000000u) ? __uint_as_float(u & 0x7fffffffu) : __uint_as_float(~u);
}
#define ENC_NEG_INF 0x007fffffu   // fenc(-inf)

// ---------------- tf32 helpers ----------------
__device__ __forceinline__ void cvt_hi_lo(float v, float& hf, float& lf) {
    uint32_t hb;
    asm("cvt.rna.tf32.f32 %0, %1;" : "=r"(hb) : "f"(v));
    hf = __uint_as_float(hb);
    float r = v - hf;
    uint32_t lb;
    asm("cvt.rna.tf32.f32 %0, %1;" : "=r"(lb) : "f"(r));
    lf = __uint_as_float(lb);
}

__device__ __forceinline__ void mma_tf32(float* d, const uint32_t* a, uint32_t b0, uint32_t b1) {
    asm volatile(
        "mma.sync.aligned.m16n8k8.row.col.f32.tf32.tf32.f32 "
        "{%0,%1,%2,%3}, {%4,%5,%6,%7}, {%8,%9}, {%0,%1,%2,%3};"
        : "+f"(d[0]), "+f"(d[1]), "+f"(d[2]), "+f"(d[3])
        : "r"(a[0]), "r"(a[1]), "r"(a[2]), "r"(a[3]), "r"(b0), "r"(b1));
}

// ---------------- TF32x3 tensor-core GEMM ----------------
// C = [relu](A@B + bias), batched over blockIdx.z.
// A: [M,K] row-major (shared across batch), B: [K,N] (+z*strideB), C: [M,N] (+z*strideC)
// Split-precision (3xTF32): fp32-level accuracy on tensor cores.
#define BM 128
#define BN 128
#define BK 16
#define AP (BM + 4)   // A tile [k][m] pad -> frag LDS conflict-free
#define BP (BN + 8)   // B tile [k][n] pad -> frag LDS conflict-free
__global__ __launch_bounds__(256) void gemm_tf32x3_kernel(
    const float* __restrict__ A, const float* __restrict__ B, float* __restrict__ C,
    const float* __restrict__ bias, int M, int N, int K, int do_relu,
    long long strideB, long long strideC)
{
    __shared__ float Ah[BK][AP];
    __shared__ float Al[BK][AP];
    __shared__ float Bh[BK][BP];
    __shared__ float Bl[BK][BP];

    const float* Bz = B + (long long)blockIdx.z * strideB;
    float*       Cz = C + (long long)blockIdx.z * strideC;

    const int tid    = threadIdx.x;
    const int lane   = tid & 31;
    const int wid    = tid >> 5;
    const int warp_m = wid >> 2;      // 0..1  (64-row band)
    const int warp_n = wid & 3;       // 0..3  (32-col band)
    const int g      = lane >> 2;     // groupID 0..7
    const int t      = lane & 3;      // threadID_in_group 0..3

    const int row0 = blockIdx.y * BM;
    const int col0 = blockIdx.x * BN;

    // global->smem load coords: 512 chunks of float4; 2 per thread
    const int a_r[2]  = { (tid + 0)   >> 2, (tid + 256) >> 2 };     // 0..127
    const int a_c4[2] = { ((tid + 0) & 3) * 4, ((tid + 256) & 3) * 4 };  // 0,4,8,12
    const int b_r[2]  = { (tid + 0)   >> 5, (tid + 256) >> 5 };     // 0..15
    const int b_c4[2] = { ((tid + 0) & 31) * 4, ((tid + 256) & 31) * 4 };

    float d[4][4][4];  // [m-frag][n-frag][reg]
#pragma unroll
    for (int mf = 0; mf < 4; mf++)
#pragma unroll
        for (int nf = 0; nf < 4; nf++)
#pragma unroll
            for (int r = 0; r < 4; r++) d[mf][nf][r] = 0.f;

    const int KT = K / BK;
    float4 ra[2], rb[2];

    // ---- load tile kt into registers ----
    auto load_regs = [&](int kt) {
        const int k0 = kt * BK;
#pragma unroll
        for (int it = 0; it < 2; it++) {
            int gr = row0 + a_r[it];
            ra[it] = make_float4(0.f, 0.f, 0.f, 0.f);
            if (gr < M) ra[it] = *(const float4*)(A + (long long)gr * K + k0 + a_c4[it]);
            rb[it] = make_float4(0.f, 0.f, 0.f, 0.f);
            int gc = col0 + b_c4[it];
            if (gc < N) rb[it] = *(const float4*)(Bz + (long long)(k0 + b_r[it]) * N + gc);
        }
    };

    // ---- convert + store registers into smem tiles ----
    auto sts_tile = [&]() {
#pragma unroll
        for (int it = 0; it < 2; it++) {
            float av[4] = { ra[it].x, ra[it].y, ra[it].z, ra[it].w };
#pragma unroll
            for (int j = 0; j < 4; j++) {
                float hf, lf;
                cvt_hi_lo(av[j], hf, lf);
                Ah[a_c4[it] + j][a_r[it]] = hf;
                Al[a_c4[it] + j][a_r[it]] = lf;
            }
            float bv[4] = { rb[it].x, rb[it].y, rb[it].z, rb[it].w };
            float4 hv, lv;
            cvt_hi_lo(bv[0], hv.x, lv.x);
            cvt_hi_lo(bv[1], hv.y, lv.y);
            cvt_hi_lo(bv[2], hv.z, lv.z);
            cvt_hi_lo(bv[3], hv.w, lv.w);
            *(float4*)&Bh[b_r[it]][b_c4[it]] = hv;
            *(float4*)&Bl[b_r[it]][b_c4[it]] = lv;
        }
    };

    load_regs(0);
    sts_tile();
    __syncthreads();

    for (int kt = 0; kt < KT; kt++) {
        if (kt + 1 < KT) load_regs(kt + 1);   // prefetch (registers only)

        // ---- compute current tile from smem ----
#pragma unroll
        for (int ks = 0; ks < BK / 8; ks++) {
            const int k0 = ks * 8 + t;
            uint32_t ah[4][4], al[4][4];
#pragma unroll
            for (int mf = 0; mf < 4; mf++) {
                int r = warp_m * 64 + mf * 16 + g;
                ah[mf][0] = __float_as_uint(Ah[k0][r]);
                ah[mf][1] = __float_as_uint(Ah[k0][r + 8]);
                ah[mf][2] = __float_as_uint(Ah[k0 + 4][r]);
                ah[mf][3] = __float_as_uint(Ah[k0 + 4][r + 8]);
                al[mf][0] = __float_as_uint(Al[k0][r]);
                al[mf][1] = __float_as_uint(Al[k0][r + 8]);
                al[mf][2] = __float_as_uint(Al[k0 + 4][r]);
                al[mf][3] = __float_as_uint(Al[k0 + 4][r + 8]);
            }
#pragma unroll
            for (int nf = 0; nf < 4; nf++) {
                int c = warp_n * 32 + nf * 8 + g;
                uint32_t bh0 = __float_as_uint(Bh[k0][c]);
                uint32_t bh1 = __float_as_uint(Bh[k0 + 4][c]);
                uint32_t bl0 = __float_as_uint(Bl[k0][c]);
                uint32_t bl1 = __float_as_uint(Bl[k0 + 4][c]);
#pragma unroll
                for (int mf = 0; mf < 4; mf++) {
                    mma_tf32(d[mf][nf], ah[mf], bl0, bl1);   // hi*lo
                    mma_tf32(d[mf][nf], al[mf], bh0, bh1);   // lo*hi
                    mma_tf32(d[mf][nf], ah[mf], bh0, bh1);   // hi*hi (largest last)
                }
            }
        }

        if (kt + 1 < KT) {
            __syncthreads();   // all warps done reading current tile
            sts_tile();        // overwrite with prefetched tile
            __syncthreads();   // tile ready
        }
    }

    // ---- epilogue: bias + relu + store (float2 per frag row-pair) ----
#pragma unroll
    for (int mf = 0; mf < 4; mf++) {
        int r0 = row0 + warp_m * 64 + mf * 16 + g;
#pragma unroll
        for (int nf = 0; nf < 4; nf++) {
            int cc = col0 + warp_n * 32 + nf * 8 + 2 * t;
            if (cc >= N) continue;
            float b0 = bias ? __ldg(bias + cc) : 0.f;
            float b1 = bias ? __ldg(bias + cc + 1) : 0.f;
            if (r0 < M) {
                float2 v = make_float2(d[mf][nf][0] + b0, d[mf][nf][1] + b1);
                if (do_relu) { v.x = fmaxf(v.x, 0.f); v.y = fmaxf(v.y, 0.f); }
                *(float2*)(Cz + (long long)r0 * N + cc) = v;
            }
            if (r0 + 8 < M) {
                float2 v = make_float2(d[mf][nf][2] + b0, d[mf][nf][3] + b1);
                if (do_relu) { v.x = fmaxf(v.x, 0.f); v.y = fmaxf(v.y, 0.f); }
                *(float2*)(Cz + (long long)(r0 + 8) * N + cc) = v;
            }
        }
    }
}

// ---------------- aq/ak: warp-per-(r,n) dual dot product ----------------
__global__ void aqak_kernel(const float* __restrict__ xw, const float* __restrict__ q,
                            const float* __restrict__ k, float* __restrict__ aq,
                            float* __restrict__ ak)
{
    int gtid = blockIdx.x * blockDim.x + threadIdx.x;
    int w    = gtid >> 5;
    int lane = gtid & 31;
    if (w >= RR * NN) return;
    const float* row = xw + (long long)w * HID;
    float sq = 0.f, sk = 0.f;
#pragma unroll
    for (int i = 0; i < HID / 32; i++) {
        float v = __ldg(row + lane + i * 32);
        sq += v * __ldg(q + lane + i * 32);
        sk += v * __ldg(k + lane + i * 32);
    }
#pragma unroll
    for (int off = 16; off; off >>= 1) {
        sq += __shfl_xor_sync(0xffffffffu, sq, off);
        sk += __shfl_xor_sync(0xffffffffu, sk, off);
    }
    if (lane == 0) { aq[w] = sq; ak[w] = sk; }
}

// ---------------- per-conv init: segment-max/denom, bias prefill ----------------
__global__ void conv_init_kernel(unsigned* __restrict__ menc, float* __restrict__ denom,
                                 float4* __restrict__ acc4, const float4* __restrict__ bias4)
{
    long long i = (long long)blockIdx.x * blockDim.x + threadIdx.x;
    if (i < NN) { menc[i] = ENC_NEG_INF; denom[i] = 0.f; }
    if (i < (long long)NN * (HID / 4)) acc4[i] = __ldg(bias4 + (i & (HID / 4 - 1)));
}

// ---------------- edge pass 1: alpha + segment max ----------------
__global__ void alpha_kernel(const int* __restrict__ src, const int* __restrict__ dst,
                             const int* __restrict__ et, const float* __restrict__ aq,
                             const float* __restrict__ ak, float* __restrict__ alpha,
                             unsigned* __restrict__ menc)
{
    int e = blockIdx.x * blockDim.x + threadIdx.x;
    if (e >= EE) return;
    int r = __ldg(et + e), d = __ldg(dst + e), s = __ldg(src + e);
    float a = __ldg(aq + (long long)r * NN + d) + __ldg(ak + (long long)r * NN + s);
    a = (a > 0.f) ? a : 0.2f * a;       // leaky_relu slope 0.2
    alpha[e] = a;
    atomicMax(menc + d, fenc(a));
}

// ---------------- edge pass 2: exp + segment sum ----------------
__global__ void ea_kernel(const int* __restrict__ dst, float* __restrict__ alpha,
                          const unsigned* __restrict__ menc, float* __restrict__ denom)
{
    int e = blockIdx.x * blockDim.x + threadIdx.x;
    if (e >= EE) return;
    int d = __ldg(dst + e);
    float v = __expf(alpha[e] - fdec(__ldg(menc + d)));
    alpha[e] = v;                        // overwrite with exp value
    atomicAdd(denom + d, v);
}

// ---------------- edge pass 3: weighted scatter (warp per edge, 128b red) ----------------
__global__ void scatter_kernel(const int* __restrict__ src, const int* __restrict__ dst,
                               const int* __restrict__ et, const float* __restrict__ ea,
                               const float* __restrict__ denom, const float* __restrict__ xw,
                               float* __restrict__ acc)
{
    int gtid = blockIdx.x * blockDim.x + threadIdx.x;
    int e    = gtid >> 5;
    int lane = gtid & 31;
    if (e >= EE) return;
    int d = __ldg(dst + e), s = __ldg(src + e), r = __ldg(et + e);
    float coef = __ldg(ea + e) / (__ldg(denom + d) + 1e-16f);
    const float4* row = (const float4*)(xw + ((long long)r * NN + s) * HID);
    float4*       out = (float4*)(acc + (long long)d * HID);
    float4 v0 = __ldg(row + lane);
    float4 v1 = __ldg(row + lane + 32);
    v0.x *= coef; v0.y *= coef; v0.z *= coef; v0.w *= coef;
    v1.x *= coef; v1.y *= coef; v1.z *= coef; v1.w *= coef;
    asm volatile("red.global.add.v4.f32 [%0], {%1, %2, %3, %4};"
                 :: "l"(out + lane), "f"(v0.x), "f"(v0.y), "f"(v0.z), "f"(v0.w)
                 : "memory");
    asm volatile("red.global.add.v4.f32 [%0], {%1, %2, %3, %4};"
                 :: "l"(out + lane + 32), "f"(v1.x), "f"(v1.y), "f"(v1.z), "f"(v1.w)
                 : "memory");
}

// ---------------- final classifier: warp per node ----------------
__global__ void cls_kernel(const float* __restrict__ h3, const float* __restrict__ w_cls,
                           const float* __restrict__ b_cls, float* __restrict__ out)
{
    int gtid = blockIdx.x * blockDim.x + threadIdx.x;
    int n    = gtid >> 5;
    int lane = gtid & 31;
    if (n >= NN) return;
    const float* row = h3 + (long long)n * OUT_F;
    float s0 = 0.f, s1 = 0.f;
#pragma unroll
    for (int i = 0; i < OUT_F / 32; i++) {
        int o = lane + i * 32;
        float v = __ldg(row + o);
        s0 += v * __ldg(w_cls + 2 * o + 0);
        s1 += v * __ldg(w_cls + 2 * o + 1);
    }
#pragma unroll
    for (int off = 16; off; off >>= 1) {
        s0 += __shfl_xor_sync(0xffffffffu, s0, off);
        s1 += __shfl_xor_sync(0xffffffffu, s1, off);
    }
    if (lane == 0) {
        out[(long long)n * 2 + 0] = s0 + b_cls[0];
        out[(long long)n * 2 + 1] = s1 + b_cls[1];
    }
}

// ---------------- host orchestration ----------------
extern "C" void kernel_launch(void* const* d_in, const int* in_sizes, int n_in,
                              void* d_out, int out_size)
{
    const float* x     = (const float*)d_in[0];
    const int*   ei    = (const int*)  d_in[1];
    const int*   et    = (const int*)  d_in[2];
    const float* w_in  = (const float*)d_in[3];
    const float* b_in  = (const float*)d_in[4];
    const float* c1w   = (const float*)d_in[5];
    const float* c1q   = (const float*)d_in[6];
    const float* c1k   = (const float*)d_in[7];
    const float* c1b   = (const float*)d_in[8];
    const float* c2w   = (const float*)d_in[9];
    const float* c2q   = (const float*)d_in[10];
    const float* c2k   = (const float*)d_in[11];
    const float* c2b   = (const float*)d_in[12];
    const float* w_out = (const float*)d_in[13];
    const float* b_out = (const float*)d_in[14];
    const float* w_cls = (const float*)d_in[15];
    const float* b_cls = (const float*)d_in[16];
    float* out = (float*)d_out;

    const int* src = ei;
    const int* dst = ei + EE;

    float *p_h, *p_h2, *p_xw, *p_aq, *p_ak, *p_alpha, *p_denom, *p_h3;
    unsigned* p_menc;
    cudaGetSymbolAddress((void**)&p_h,    g_h);
    cudaGetSymbolAddress((void**)&p_h2,   g_h2);
    cudaGetSymbolAddress((void**)&p_xw,   g_xw);
    cudaGetSymbolAddress((void**)&p_aq,   g_aq);
    cudaGetSymbolAddress((void**)&p_ak,   g_ak);
    cudaGetSymbolAddress((void**)&p_alpha,g_alpha);
    cudaGetSymbolAddress((void**)&p_menc, g_menc);
    cudaGetSymbolAddress((void**)&p_denom,g_denom);
    cudaGetSymbolAddress((void**)&p_h3,   g_h3);

    const int GY = (NN + BM - 1) / BM;         // 391
    const long long nvec = (long long)NN * (HID / 4);

    // h = relu(x @ w_in + b_in)
    gemm_tf32x3_kernel<<<dim3((HID + BN - 1) / BN, GY, 1), 256>>>(
        x, w_in, p_h, b_in, NN, HID, IN_F, 1, 0, 0);

    // two RGAT convs
    const float* cw[2] = {c1w, c2w};
    const float* cq[2] = {c1q, c2q};
    const float* ck[2] = {c1k, c2k};
    const float* cb[2] = {c1b, c2b};
    float* hin[2]  = {p_h,  p_h2};
    float* hout[2] = {p_h2, p_h};

    for (int l = 0; l < 2; l++) {
        // init segment max / denom + pre-fill output with broadcast bias
        conv_init_kernel<<<(int)((nvec + 255) / 256), 256>>>(
            p_menc, p_denom, (float4*)hout[l], (const float4*)cb[l]);
        // xw[r] = h @ W[r]  (batched over z)
        gemm_tf32x3_kernel<<<dim3((HID + BN - 1) / BN, GY, RR), 256>>>(
            hin[l], cw[l], p_xw, nullptr, NN, HID, HID, 0,
            (long long)HID * HID, (long long)NN * HID);
        aqak_kernel<<<(RR * NN * 32 + 255) / 256, 256>>>(p_xw, cq[l], ck[l], p_aq, p_ak);
        alpha_kernel<<<(EE + 255) / 256, 256>>>(src, dst, et, p_aq, p_ak, p_alpha, p_menc);
        ea_kernel<<<(EE + 255) / 256, 256>>>(dst, p_alpha, p_menc, p_denom);
        scatter_kernel<<<((size_t)EE * 32 + 255) / 256, 256>>>(
            src, dst, et, p_alpha, p_denom, p_xw, hout[l]);
    }

    // h3 = relu(h @ w_out + b_out)
    gemm_tf32x3_kernel<<<dim3(1, GY, 1), 256>>>(
        p_h, w_out, p_h3, b_out, NN, OUT_F, HID, 1, 0, 0);
    // out = h3 @ w_cls + b_cls
    cls_kernel<<<((size_t)NN * 32 + 255) / 256, 256>>>(p_h3, w_cls, b_cls, out);
}